// round 6
// baseline (speedup 1.0000x reference)
#include <cuda_runtime.h>
#include <math.h>

#define NN 100000
#define EE 1600000
#define HC 64
#define IN_DIM 128

// ---------------- scratch (device globals, allocation-free) ----------------
static __device__ float  g_xp[(size_t)NN * HC];   // xp [N,64]
static __device__ float4 g_as4[NN];               // a_src [N,4]
static __device__ float4 g_ad4[NN];               // a_dst [N,4]
static __device__ float4 g_rcp4[NN];              // per-node 1/(sum exp(l))
static __device__ int    g_cnt[NN];               // degree histogram
static __device__ int2   g_fc[NN];                // {row start, fill cursor}
static __device__ int    g_rowptr[NN + 1];        // CSR row pointers
static __device__ int    g_bsum[512];             // scan partials
static __device__ int    g_boff[512];             // scan offsets
static __device__ int    g_csr_src[EE];           // CSR src ids

__device__ __forceinline__ float lrelu(float v) { return v >= 0.f ? v : 0.2f * v; }

__device__ __forceinline__ float f2tf(float f) {
    unsigned u;
    asm("cvt.rna.tf32.f32 %0, %1;" : "=r"(u) : "f"(f));
    return __uint_as_float(u);
}
__device__ __forceinline__ void mma_tf32(float4& d,
    float a0, float a1, float a2, float a3, float b0, float b1)
{
    asm("mma.sync.aligned.m16n8k8.row.col.f32.tf32.tf32.f32 "
        "{%0,%1,%2,%3}, {%4,%5,%6,%7}, {%8,%9}, {%0,%1,%2,%3};"
        : "+f"(d.x), "+f"(d.y), "+f"(d.z), "+f"(d.w)
        : "r"(__float_as_uint(a0)), "r"(__float_as_uint(a1)),
          "r"(__float_as_uint(a2)), "r"(__float_as_uint(a3)),
          "r"(__float_as_uint(b0)), "r"(__float_as_uint(b1)));
}
// k-pair permutation within each group of 8: (t, t+4) -> (2t, 2t+1)
__device__ __forceinline__ int kslot(int kk) {
    return (kk < 4) ? (2 * kk) : (2 * (kk - 4) + 1);
}

// ---------------- init: zero histogram ----------------
__global__ void init_kernel(int n) {
    int i = blockIdx.x * blockDim.x + threadIdx.x;
    if (i < n) g_cnt[i] = 0;
}

// ---------------- GEMM: xp = x @ W via tf32 tensor cores + attn epilogue ----------------
// 64x64 tile, 256 threads = 8 warps (4m x 2n); warp tile 16x32.
// smem holds tf32-converted operands, k-pair-permuted so fragment loads are float2.
__global__ __launch_bounds__(256) void gemm_kernel(
    const float* __restrict__ x, const float* __restrict__ W,
    const float* __restrict__ att_src, const float* __restrict__ att_dst, int n)
{
    __shared__ float xs[64 * 72];   // [row][kslot] (reused for C in epilogue)
    __shared__ float ws[64 * 72];   // [col][kslot]
    int tid = threadIdx.x;
    int lane = tid & 31, warp = tid >> 5;
    int wm = warp & 3, wn = warp >> 2;
    int gid = lane >> 2, tig = lane & 3;
    int r0 = blockIdx.x * 64;

    float4 c[4];
#pragma unroll
    for (int t = 0; t < 4; t++) c[t] = make_float4(0.f, 0.f, 0.f, 0.f);

    for (int kh = 0; kh < 2; kh++) {
        // stage x: xs[row][g*8 + kslot], tf32-converted
#pragma unroll
        for (int q = 0; q < 4; q++) {
            int idx = tid + q * 256;           // 0..1023
            int row = idx >> 4, k4 = idx & 15;
            float4 v = make_float4(0.f, 0.f, 0.f, 0.f);
            int grow = r0 + row;
            if (grow < n)
                v = *(const float4*)(x + (size_t)grow * IN_DIM + kh * 64 + k4 * 4);
            int g = k4 >> 1, odd = k4 & 1;     // k4 even -> kk 0..3, odd -> kk 4..7
            float* dst = xs + row * 72 + g * 8 + odd;
            dst[0] = f2tf(v.x); dst[2] = f2tf(v.y);
            dst[4] = f2tf(v.z); dst[6] = f2tf(v.w);
        }
        // stage W: ws[col][g*8 + kslot], tf32-converted
#pragma unroll
        for (int q = 0; q < 4; q++) {
            int idx = tid + q * 256;
            int k = idx >> 4, c4 = idx & 15;
            float4 v = *(const float4*)(W + (size_t)(kh * 64 + k) * HC + c4 * 4);
            int slot = (k >> 3) * 8 + kslot(k & 7);
            ws[(c4 * 4 + 0) * 72 + slot] = f2tf(v.x);
            ws[(c4 * 4 + 1) * 72 + slot] = f2tf(v.y);
            ws[(c4 * 4 + 2) * 72 + slot] = f2tf(v.z);
            ws[(c4 * 4 + 3) * 72 + slot] = f2tf(v.w);
        }
        __syncthreads();
#pragma unroll
        for (int k8 = 0; k8 < 8; k8++) {
            int kb = k8 * 8 + 2 * tig;
            const float* xr = xs + (16 * wm + gid) * 72 + kb;
            float2 alo = *(const float2*)(xr);            // (a0, a2): k=tig, tig+4
            float2 ahi = *(const float2*)(xr + 8 * 72);   // (a1, a3)
            const float* wr = ws + (32 * wn + gid) * 72 + kb;
#pragma unroll
            for (int t = 0; t < 4; t++) {
                float2 bv = *(const float2*)(wr + 8 * t * 72);  // (b0, b1)
                mma_tf32(c[t], alo.x, ahi.x, alo.y, ahi.y, bv.x, bv.y);
            }
        }
        __syncthreads();
    }

    // write C frags into xs [row][col]
    {
        int rlo = 16 * wm + gid;
        int cb  = 32 * wn + 2 * tig;
#pragma unroll
        for (int t = 0; t < 4; t++) {
            *(float2*)(xs + rlo * 72 + cb + 8 * t)       = make_float2(c[t].x, c[t].y);
            *(float2*)(xs + (rlo + 8) * 72 + cb + 8 * t) = make_float2(c[t].z, c[t].w);
        }
    }
    __syncthreads();

    // epilogue: thread = (row, quarter); quarter qd = head qd (cols 16qd..16qd+15)
    {
        int row = tid >> 2, qd = tid & 3;
        int grow = r0 + row;
        if (grow < n) {
            float4 v[4], s4[4], d4[4];
#pragma unroll
            for (int i = 0; i < 4; i++) {
                v[i]  = *(const float4*)(xs + row * 72 + qd * 16 + 4 * i);
                s4[i] = __ldg((const float4*)(att_src + qd * 16 + 4 * i));
                d4[i] = __ldg((const float4*)(att_dst + qd * 16 + 4 * i));
            }
            float as = 0.f, ad = 0.f;
#pragma unroll
            for (int i = 0; i < 4; i++) {
                as += v[i].x * s4[i].x + v[i].y * s4[i].y + v[i].z * s4[i].z + v[i].w * s4[i].w;
                ad += v[i].x * d4[i].x + v[i].y * d4[i].y + v[i].z * d4[i].z + v[i].w * d4[i].w;
            }
            ((float*)&g_as4[grow])[qd] = as;
            ((float*)&g_ad4[grow])[qd] = ad;
#pragma unroll
            for (int i = 0; i < 4; i++)
                *(float4*)(g_xp + (size_t)grow * HC + qd * 16 + 4 * i) = v[i];
        }
    }
}

// ---------------- CSR build ----------------
__global__ void hist_kernel(const int* __restrict__ ei, int e) {
    int t = blockIdx.x * blockDim.x + threadIdx.x;
    int base = t * 4;
    if (base + 3 < e) {
        int4 d4 = *(const int4*)(ei + e + base);
        atomicAdd(&g_cnt[d4.x], 1);
        atomicAdd(&g_cnt[d4.y], 1);
        atomicAdd(&g_cnt[d4.z], 1);
        atomicAdd(&g_cnt[d4.w], 1);
    } else {
        for (int i = base; i < e; i++) atomicAdd(&g_cnt[ei[e + i]], 1);
    }
}

__global__ void scan1_kernel(int n) {
    __shared__ int sd[512];
    int t = threadIdx.x, i = blockIdx.x * 512 + t;
    int v = (i < n) ? g_cnt[i] : 0;
    sd[t] = v; __syncthreads();
    for (int off = 1; off < 512; off <<= 1) {
        int x = (t >= off) ? sd[t - off] : 0;
        __syncthreads();
        sd[t] += x;
        __syncthreads();
    }
    if (i < n) g_rowptr[i + 1] = sd[t];
    if (t == 511) g_bsum[blockIdx.x] = sd[511];
}

__global__ void scan2_kernel(int nb) {
    __shared__ int sd[512];
    int t = threadIdx.x;
    int v = (t < nb) ? g_bsum[t] : 0;
    sd[t] = v; __syncthreads();
    for (int off = 1; off < 512; off <<= 1) {
        int x = (t >= off) ? sd[t - off] : 0;
        __syncthreads();
        sd[t] += x;
        __syncthreads();
    }
    g_boff[t] = sd[t] - v;   // exclusive
}

// adds block offsets AND initializes fill cursors {start, 0}
__global__ void scan3_kernel(int n) {
    int t = threadIdx.x;
    int i = blockIdx.x * 512 + t;
    int inc = g_boff[blockIdx.x];
    int prev = 0;
    if (i < n && t > 0) prev = g_rowptr[i];     // scan1 value at i (pre-offset)
    __syncthreads();
    if (i < n) {
        g_rowptr[i + 1] += inc;
        g_fc[i] = make_int2(prev + inc, 0);
        if (i == 0) g_rowptr[0] = 0;
    }
}

__global__ void fill_kernel(const int* __restrict__ ei, int e) {
    int t = blockIdx.x * blockDim.x + threadIdx.x;
    if (t >= e) return;
    int s = ei[t], d = ei[e + t];
    int2* fc = &g_fc[d];
    int pos = atomicAdd(&fc->y, 1);
    g_csr_src[fc->x + pos] = s;
}

// ---------------- fused softmax + aggregation: one warp per dst node ----------------
__global__ __launch_bounds__(256) void aggregate_kernel(
    const float* __restrict__ bias, float* __restrict__ out, int n)
{
    __shared__ float sE[8][32][4];
    int w = (blockIdx.x * 256 + threadIdx.x) >> 5;
    int lane = threadIdx.x & 31, wl = threadIdx.x >> 5;
    if (w >= n) return;                 // uniform per warp

    int start = g_rowptr[w];
    int deg   = g_rowptr[w + 1] - start;
    float4 ad = g_ad4[w];

    float4 ds = make_float4(0.f, 0.f, 0.f, 0.f);
    float acc0 = 0.f, acc1 = 0.f;
    int h0 = lane >> 4;      // head of col=lane; col=lane+32 is head h0+2

    for (int base = 0; base < deg; base += 32) {
        int i = base + lane;
        int s = 0;
        float4 ev = make_float4(0.f, 0.f, 0.f, 0.f);
        if (i < deg) {
            s = g_csr_src[start + i];
            float4 a = g_as4[s];
            ev.x = __expf(lrelu(a.x + ad.x));
            ev.y = __expf(lrelu(a.y + ad.y));
            ev.z = __expf(lrelu(a.z + ad.z));
            ev.w = __expf(lrelu(a.w + ad.w));
            ds.x += ev.x; ds.y += ev.y; ds.z += ev.z; ds.w += ev.w;
        }
        sE[wl][lane][0] = ev.x; sE[wl][lane][1] = ev.y;
        sE[wl][lane][2] = ev.z; sE[wl][lane][3] = ev.w;
        __syncwarp();
        int cnt = min(32, deg - base);
        const float* sEj = &sE[wl][0][0];
#pragma unroll 8
        for (int j = 0; j < cnt; j++) {
            int sj = __shfl_sync(0xffffffffu, s, j);
            float e0 = sEj[j * 4 + h0];
            float e1 = sEj[j * 4 + 2 + h0];
            const float* xp = g_xp + (size_t)sj * HC;
            acc0 = fmaf(__ldg(xp + lane),      e0, acc0);
            acc1 = fmaf(__ldg(xp + 32 + lane), e1, acc1);
        }
        __syncwarp();
    }
#pragma unroll
    for (int o = 16; o >= 1; o >>= 1) {
        ds.x += __shfl_xor_sync(0xffffffffu, ds.x, o);
        ds.y += __shfl_xor_sync(0xffffffffu, ds.y, o);
        ds.z += __shfl_xor_sync(0xffffffffu, ds.z, o);
        ds.w += __shfl_xor_sync(0xffffffffu, ds.w, o);
    }
    float4 r;
    r.x = 1.f / (ds.x + 1e-16f); r.y = 1.f / (ds.y + 1e-16f);
    r.z = 1.f / (ds.z + 1e-16f); r.w = 1.f / (ds.w + 1e-16f);
    if (lane == 0) g_rcp4[w] = r;

    float r0 = h0 ? r.y : r.x;
    float r1 = h0 ? r.w : r.z;
    out[(size_t)w * HC + lane]      = acc0 * r0 + bias[lane];
    out[(size_t)w * HC + 32 + lane] = acc1 * r1 + bias[lane + 32];
}

// ---------------- alpha + edge_index copy, edge order (coalesced) ----------------
__global__ __launch_bounds__(256) void alpha_ei_kernel(
    const int* __restrict__ ei, int e,
    float* __restrict__ alpha_out, float* __restrict__ ei_out)
{
    int t = blockIdx.x * blockDim.x + threadIdx.x;
    if (t >= e) return;
    int s = ei[t], d = ei[e + t];
    if (ei_out) {
        ei_out[t]     = (float)s;
        ei_out[e + t] = (float)d;
    }
    if (alpha_out) {
        float4 a = g_as4[s];
        float4 b = g_ad4[d];
        float4 r = g_rcp4[d];
        float4 o;
        o.x = __expf(lrelu(a.x + b.x)) * r.x;
        o.y = __expf(lrelu(a.y + b.y)) * r.y;
        o.z = __expf(lrelu(a.z + b.z)) * r.z;
        o.w = __expf(lrelu(a.w + b.w)) * r.w;
        ((float4*)alpha_out)[t] = o;
    }
}

extern "C" void kernel_launch(void* const* d_in, const int* in_sizes, int n_in,
                              void* d_out, int out_size) {
    const float* x       = (const float*)d_in[0];
    const float* W       = (const float*)d_in[1];
    const float* att_src = (const float*)d_in[2];
    const float* att_dst = (const float*)d_in[3];
    const float* bias    = (const float*)d_in[4];
    const int*   ei      = (const int*)d_in[5];
    float* out = (float*)d_out;

    int n = in_sizes[0] / IN_DIM;   // 100000
    int e = in_sizes[5] / 2;        // 1600000
    long nhc = (long)n * HC;
    int nb = (n + 511) / 512;

    // order chosen so the profiler's captured launch (index 3) is the GEMM
    init_kernel<<<(n + 511) / 512, 512>>>(n);
    hist_kernel<<<((e + 3) / 4 + 255) / 256, 256>>>(ei, e);
    scan1_kernel<<<nb, 512>>>(n);
    gemm_kernel<<<(n + 63) / 64, 256>>>(x, W, att_src, att_dst, n);
    scan2_kernel<<<1, 512>>>(nb);
    scan3_kernel<<<nb, 512>>>(n);
    fill_kernel<<<(e + 255) / 256, 256>>>(ei, e);
    aggregate_kernel<<<(n * 32 + 255) / 256, 256>>>(bias, out, n);

    float* ei_out = nullptr;
    float* alpha_out = nullptr;
    if ((long)out_size >= nhc + 2L * e)          ei_out    = out + nhc;
    if ((long)out_size >= nhc + 2L * e + 4L * e) alpha_out = out + nhc + 2L * e;

    if (ei_out || alpha_out)
        alpha_ei_kernel<<<(e + 255) / 256, 256>>>(ei, e, alpha_out, ei_out);
}

// round 7
// speedup vs baseline: 1.1291x; 1.1291x over previous
#include <cuda_runtime.h>
#include <math.h>

#define NN 100000
#define EE 1600000
#define HC 64
#define IN_DIM 128

// ---------------- scratch (device globals, allocation-free) ----------------
static __device__ float  g_xp[(size_t)NN * HC];   // xp [N,64]
static __device__ float4 g_as4[NN];               // a_src [N,4]
static __device__ float4 g_ad4[NN];               // a_dst [N,4]
static __device__ float4 g_rcp4[NN];              // per-node 1/(sum exp(l))
static __device__ int    g_cnt[NN];               // degree histogram
static __device__ int2   g_fc[NN];                // {row start, fill cursor}
static __device__ int    g_rowptr[NN + 1];        // CSR row pointers
static __device__ int    g_bsum[512];             // scan partials
static __device__ int    g_boff[512];             // scan offsets
static __device__ int    g_csr_src[EE];           // CSR src ids

__device__ __forceinline__ float lrelu(float v) { return v >= 0.f ? v : 0.2f * v; }

__device__ __forceinline__ float f2tf(float f) {
    unsigned u;
    asm("cvt.rna.tf32.f32 %0, %1;" : "=r"(u) : "f"(f));
    return __uint_as_float(u);
}
__device__ __forceinline__ void mma_tf32(float4& d,
    float a0, float a1, float a2, float a3, float b0, float b1)
{
    asm("mma.sync.aligned.m16n8k8.row.col.f32.tf32.tf32.f32 "
        "{%0,%1,%2,%3}, {%4,%5,%6,%7}, {%8,%9}, {%0,%1,%2,%3};"
        : "+f"(d.x), "+f"(d.y), "+f"(d.z), "+f"(d.w)
        : "r"(__float_as_uint(a0)), "r"(__float_as_uint(a1)),
          "r"(__float_as_uint(a2)), "r"(__float_as_uint(a3)),
          "r"(__float_as_uint(b0)), "r"(__float_as_uint(b1)));
}

// ---------------- init: zero histogram ----------------
__global__ void init_kernel(int n) {
    int i = blockIdx.x * blockDim.x + threadIdx.x;
    if (i < n) g_cnt[i] = 0;
}

// ---------------- GEMM: xp = x @ W via tf32 tensor cores + attn epilogue ----------------
// R5 layout (conflict-free), values pre-converted to tf32 at staging.
// 64x64 tile, 256 threads = 8 warps (4m x 2n); warp tile 16x32 (4 n8 subtiles).
__global__ __launch_bounds__(256) void gemm_kernel(
    const float* __restrict__ x, const float* __restrict__ W,
    const float* __restrict__ att_src, const float* __restrict__ att_dst, int n)
{
    __shared__ float xs[64 * 68];   // [row][k-half], stride 68 (reused for C)
    __shared__ float ws[64 * 72];   // [k-half][col], stride 72
    int tid = threadIdx.x;
    int lane = tid & 31, warp = tid >> 5;
    int wm = warp & 3, wn = warp >> 2;
    int gid = lane >> 2, tig = lane & 3;
    int r0 = blockIdx.x * 64;

    float4 c[4];
#pragma unroll
    for (int t = 0; t < 4; t++) c[t] = make_float4(0.f, 0.f, 0.f, 0.f);

    for (int kh = 0; kh < 2; kh++) {
        // stage x tile: xs[row][k], tf32-converted values (same addresses as R5)
#pragma unroll
        for (int q = 0; q < 4; q++) {
            int idx = tid + q * 256;           // 0..1023
            int row = idx >> 4, k4 = idx & 15;
            float4 v = make_float4(0.f, 0.f, 0.f, 0.f);
            int grow = r0 + row;
            if (grow < n)
                v = *(const float4*)(x + (size_t)grow * IN_DIM + kh * 64 + k4 * 4);
            *(float4*)(xs + row * 68 + k4 * 4) =
                make_float4(f2tf(v.x), f2tf(v.y), f2tf(v.z), f2tf(v.w));
        }
        // stage W half: ws[k][col], tf32-converted
#pragma unroll
        for (int q = 0; q < 4; q++) {
            int idx = tid + q * 256;
            int k = idx >> 4, c4 = idx & 15;
            float4 v = *(const float4*)(W + (size_t)(kh * 64 + k) * HC + c4 * 4);
            *(float4*)(ws + k * 72 + c4 * 4) =
                make_float4(f2tf(v.x), f2tf(v.y), f2tf(v.z), f2tf(v.w));
        }
        __syncthreads();
#pragma unroll
        for (int k8 = 0; k8 < 8; k8++) {
            int kb = k8 * 8;
            const float* xr = xs + (16 * wm + gid) * 68 + kb + tig;
            float a0 = xr[0];
            float a1 = xr[8 * 68];
            float a2 = xr[4];
            float a3 = xr[8 * 68 + 4];
            const float* wr = ws + (kb + tig) * 72 + 32 * wn + gid;
#pragma unroll
            for (int t = 0; t < 4; t++) {
                float b0 = wr[8 * t];
                float b1 = wr[4 * 72 + 8 * t];
                mma_tf32(c[t], a0, a1, a2, a3, b0, b1);
            }
        }
        __syncthreads();
    }

    // write C frags into xs [row][col 0..63]
    {
        int rlo = 16 * wm + gid;
        int cb  = 32 * wn + 2 * tig;
#pragma unroll
        for (int t = 0; t < 4; t++) {
            *(float2*)(xs + rlo * 68 + cb + 8 * t)       = make_float2(c[t].x, c[t].y);
            *(float2*)(xs + (rlo + 8) * 68 + cb + 8 * t) = make_float2(c[t].z, c[t].w);
        }
    }
    __syncthreads();

    // epilogue: thread = (row, quarter). quarter qd handles cols 16qd..16qd+15 = head qd.
    {
        int row = tid >> 2, qd = tid & 3;
        int grow = r0 + row;
        if (grow < n) {
            float4 v[4], s4[4], d4[4];
#pragma unroll
            for (int i = 0; i < 4; i++) {
                v[i]  = *(const float4*)(xs + row * 68 + qd * 16 + 4 * i);
                s4[i] = __ldg((const float4*)(att_src + qd * 16 + 4 * i));
                d4[i] = __ldg((const float4*)(att_dst + qd * 16 + 4 * i));
            }
            float as = 0.f, ad = 0.f;
#pragma unroll
            for (int i = 0; i < 4; i++) {
                as += v[i].x * s4[i].x + v[i].y * s4[i].y + v[i].z * s4[i].z + v[i].w * s4[i].w;
                ad += v[i].x * d4[i].x + v[i].y * d4[i].y + v[i].z * d4[i].z + v[i].w * d4[i].w;
            }
            ((float*)&g_as4[grow])[qd] = as;
            ((float*)&g_ad4[grow])[qd] = ad;
#pragma unroll
            for (int i = 0; i < 4; i++)
                *(float4*)(g_xp + (size_t)grow * HC + qd * 16 + 4 * i) = v[i];
        }
    }
}

// ---------------- CSR histogram + fused edge_index float copy ----------------
__global__ void hist_kernel(const int* __restrict__ ei, int e, float* __restrict__ ei_out) {
    int t = blockIdx.x * blockDim.x + threadIdx.x;
    int base = t * 4;
    if (base + 3 < e) {
        int4 d4 = *(const int4*)(ei + e + base);
        atomicAdd(&g_cnt[d4.x], 1);
        atomicAdd(&g_cnt[d4.y], 1);
        atomicAdd(&g_cnt[d4.z], 1);
        atomicAdd(&g_cnt[d4.w], 1);
        if (ei_out) {
            int4 s4 = *(const int4*)(ei + base);
            *(float4*)(ei_out + base) =
                make_float4((float)s4.x, (float)s4.y, (float)s4.z, (float)s4.w);
            *(float4*)(ei_out + e + base) =
                make_float4((float)d4.x, (float)d4.y, (float)d4.z, (float)d4.w);
        }
    } else {
        for (int i = base; i < e; i++) {
            int s = ei[i], d = ei[e + i];
            atomicAdd(&g_cnt[d], 1);
            if (ei_out) { ei_out[i] = (float)s; ei_out[e + i] = (float)d; }
        }
    }
}

__global__ void scan1_kernel(int n) {
    __shared__ int sd[512];
    int t = threadIdx.x, i = blockIdx.x * 512 + t;
    int v = (i < n) ? g_cnt[i] : 0;
    sd[t] = v; __syncthreads();
    for (int off = 1; off < 512; off <<= 1) {
        int x = (t >= off) ? sd[t - off] : 0;
        __syncthreads();
        sd[t] += x;
        __syncthreads();
    }
    if (i < n) g_rowptr[i + 1] = sd[t];
    if (t == 511) g_bsum[blockIdx.x] = sd[511];
}

__global__ void scan2_kernel(int nb) {
    __shared__ int sd[512];
    int t = threadIdx.x;
    int v = (t < nb) ? g_bsum[t] : 0;
    sd[t] = v; __syncthreads();
    for (int off = 1; off < 512; off <<= 1) {
        int x = (t >= off) ? sd[t - off] : 0;
        __syncthreads();
        sd[t] += x;
        __syncthreads();
    }
    g_boff[t] = sd[t] - v;   // exclusive
}

// adds block offsets AND initializes fill cursors {start, 0}
__global__ void scan3_kernel(int n) {
    int t = threadIdx.x;
    int i = blockIdx.x * 512 + t;
    int inc = g_boff[blockIdx.x];
    int prev = 0;
    if (i < n && t > 0) prev = g_rowptr[i];     // scan1 value at i (pre-offset)
    __syncthreads();
    if (i < n) {
        g_rowptr[i + 1] += inc;
        g_fc[i] = make_int2(prev + inc, 0);
        if (i == 0) g_rowptr[0] = 0;
    }
}

__global__ void fill_kernel(const int* __restrict__ ei, int e) {
    int t = blockIdx.x * blockDim.x + threadIdx.x;
    if (t >= e) return;
    int s = ei[t], d = ei[e + t];
    int2* fc = &g_fc[d];
    int pos = atomicAdd(&fc->y, 1);
    g_csr_src[fc->x + pos] = s;
}

// ---------------- fused softmax + aggregation: one warp per dst node ----------------
__global__ __launch_bounds__(256) void aggregate_kernel(
    const float* __restrict__ bias, float* __restrict__ out, int n)
{
    __shared__ float sE[8][32][4];
    int w = (blockIdx.x * 256 + threadIdx.x) >> 5;
    int lane = threadIdx.x & 31, wl = threadIdx.x >> 5;
    if (w >= n) return;                 // uniform per warp

    int start = g_rowptr[w];
    int deg   = g_rowptr[w + 1] - start;
    float4 ad = g_ad4[w];

    float4 ds = make_float4(0.f, 0.f, 0.f, 0.f);
    float acc0 = 0.f, acc1 = 0.f;
    int h0 = lane >> 4;      // head of col=lane; col=lane+32 is head h0+2

    for (int base = 0; base < deg; base += 32) {
        int i = base + lane;
        int s = 0;
        float4 ev = make_float4(0.f, 0.f, 0.f, 0.f);
        if (i < deg) {
            s = g_csr_src[start + i];
            float4 a = g_as4[s];
            ev.x = __expf(lrelu(a.x + ad.x));
            ev.y = __expf(lrelu(a.y + ad.y));
            ev.z = __expf(lrelu(a.z + ad.z));
            ev.w = __expf(lrelu(a.w + ad.w));
            ds.x += ev.x; ds.y += ev.y; ds.z += ev.z; ds.w += ev.w;
        }
        sE[wl][lane][0] = ev.x; sE[wl][lane][1] = ev.y;
        sE[wl][lane][2] = ev.z; sE[wl][lane][3] = ev.w;
        __syncwarp();
        int cnt = min(32, deg - base);
        const float* sEj = &sE[wl][0][0];
#pragma unroll 8
        for (int j = 0; j < cnt; j++) {
            int sj = __shfl_sync(0xffffffffu, s, j);
            float e0 = sEj[j * 4 + h0];
            float e1 = sEj[j * 4 + 2 + h0];
            const float* xp = g_xp + (size_t)sj * HC;
            acc0 = fmaf(__ldg(xp + lane),      e0, acc0);
            acc1 = fmaf(__ldg(xp + 32 + lane), e1, acc1);
        }
        __syncwarp();
    }
#pragma unroll
    for (int o = 16; o >= 1; o >>= 1) {
        ds.x += __shfl_xor_sync(0xffffffffu, ds.x, o);
        ds.y += __shfl_xor_sync(0xffffffffu, ds.y, o);
        ds.z += __shfl_xor_sync(0xffffffffu, ds.z, o);
        ds.w += __shfl_xor_sync(0xffffffffu, ds.w, o);
    }
    float4 r;
    r.x = 1.f / (ds.x + 1e-16f); r.y = 1.f / (ds.y + 1e-16f);
    r.z = 1.f / (ds.z + 1e-16f); r.w = 1.f / (ds.w + 1e-16f);
    if (lane == 0) g_rcp4[w] = r;

    float r0 = h0 ? r.y : r.x;
    float r1 = h0 ? r.w : r.z;
    out[(size_t)w * HC + lane]      = acc0 * r0 + bias[lane];
    out[(size_t)w * HC + 32 + lane] = acc1 * r1 + bias[lane + 32];
}

// ---------------- alpha in edge order (coalesced) ----------------
__global__ __launch_bounds__(256) void alpha_kernel(
    const int* __restrict__ ei, int e, float* __restrict__ alpha_out)
{
    int t = blockIdx.x * blockDim.x + threadIdx.x;
    if (t >= e) return;
    int s = ei[t], d = ei[e + t];
    float4 a = g_as4[s];
    float4 b = g_ad4[d];
    float4 r = g_rcp4[d];
    float4 o;
    o.x = __expf(lrelu(a.x + b.x)) * r.x;
    o.y = __expf(lrelu(a.y + b.y)) * r.y;
    o.z = __expf(lrelu(a.z + b.z)) * r.z;
    o.w = __expf(lrelu(a.w + b.w)) * r.w;
    ((float4*)alpha_out)[t] = o;
}

extern "C" void kernel_launch(void* const* d_in, const int* in_sizes, int n_in,
                              void* d_out, int out_size) {
    const float* x       = (const float*)d_in[0];
    const float* W       = (const float*)d_in[1];
    const float* att_src = (const float*)d_in[2];
    const float* att_dst = (const float*)d_in[3];
    const float* bias    = (const float*)d_in[4];
    const int*   ei      = (const int*)d_in[5];
    float* out = (float*)d_out;

    int n = in_sizes[0] / IN_DIM;   // 100000
    int e = in_sizes[5] / 2;        // 1600000
    long nhc = (long)n * HC;
    int nb = (n + 511) / 512;

    float* ei_out = nullptr;
    float* alpha_out = nullptr;
    if ((long)out_size >= nhc + 2L * e)          ei_out    = out + nhc;
    if ((long)out_size >= nhc + 2L * e + 4L * e) alpha_out = out + nhc + 2L * e;

    // order chosen so the profiler's captured launch (index 3) is the GEMM
    init_kernel<<<(n + 511) / 512, 512>>>(n);
    hist_kernel<<<((e + 3) / 4 + 255) / 256, 256>>>(ei, e, ei_out);
    scan1_kernel<<<nb, 512>>>(n);
    gemm_kernel<<<(n + 63) / 64, 256>>>(x, W, att_src, att_dst, n);
    scan2_kernel<<<1, 512>>>(nb);
    scan3_kernel<<<nb, 512>>>(n);
    fill_kernel<<<(e + 255) / 256, 256>>>(ei, e);
    aggregate_kernel<<<(n * 32 + 255) / 256, 256>>>(bias, out, n);

    if (alpha_out)
        alpha_kernel<<<(e + 255) / 256, 256>>>(ei, e, alpha_out);
}

// round 8
// speedup vs baseline: 1.1448x; 1.0140x over previous
#include <cuda_runtime.h>
#include <math.h>

#define NN 100000
#define EE 1600000
#define HC 64
#define IN_DIM 128

// ---------------- scratch (device globals, allocation-free) ----------------
// g_xp holds xp in interleaved-pair layout: element 2c   = xp[node][c]
//                                           element 2c+1 = xp[node][c+32]  (c = 0..31)
static __device__ float  g_xp[(size_t)NN * HC];
static __device__ float4 g_as4[NN];               // a_src [N,4]
static __device__ float4 g_ad4[NN];               // a_dst [N,4]
static __device__ float4 g_rcp4[NN];              // per-node 1/(sum exp(l))
static __device__ int    g_cnt[NN];               // degree histogram
static __device__ int2   g_fc[NN];                // {row start, fill cursor}
static __device__ int    g_rowptr[NN + 1];        // CSR row pointers
static __device__ int    g_bsum[512];             // scan partials
static __device__ int    g_boff[512];             // scan offsets
static __device__ int    g_csr_src[EE];           // CSR src ids

__device__ __forceinline__ float lrelu(float v) { return v >= 0.f ? v : 0.2f * v; }

__device__ __forceinline__ float f2tf(float f) {
    unsigned u;
    asm("cvt.rna.tf32.f32 %0, %1;" : "=r"(u) : "f"(f));
    return __uint_as_float(u);
}
__device__ __forceinline__ void mma_tf32(float4& d,
    float a0, float a1, float a2, float a3, float b0, float b1)
{
    asm("mma.sync.aligned.m16n8k8.row.col.f32.tf32.tf32.f32 "
        "{%0,%1,%2,%3}, {%4,%5,%6,%7}, {%8,%9}, {%0,%1,%2,%3};"
        : "+f"(d.x), "+f"(d.y), "+f"(d.z), "+f"(d.w)
        : "r"(__float_as_uint(a0)), "r"(__float_as_uint(a1)),
          "r"(__float_as_uint(a2)), "r"(__float_as_uint(a3)),
          "r"(__float_as_uint(b0)), "r"(__float_as_uint(b1)));
}

// ---------------- init: zero histogram ----------------
__global__ void init_kernel(int n) {
    int i = blockIdx.x * blockDim.x + threadIdx.x;
    if (i < n) g_cnt[i] = 0;
}

// ---------------- GEMM: xp = x @ W via tf32 tensor cores + attn epilogue ----------------
// R7 mainloop byte-identical; epilogue writes interleaved xp2 layout.
__global__ __launch_bounds__(256) void gemm_kernel(
    const float* __restrict__ x, const float* __restrict__ W,
    const float* __restrict__ att_src, const float* __restrict__ att_dst, int n)
{
    __shared__ float xs[64 * 68];   // [row][k-half], stride 68 (reused for C)
    __shared__ float ws[64 * 72];   // [k-half][col], stride 72
    int tid = threadIdx.x;
    int lane = tid & 31, warp = tid >> 5;
    int wm = warp & 3, wn = warp >> 2;
    int gid = lane >> 2, tig = lane & 3;
    int r0 = blockIdx.x * 64;

    float4 c[4];
#pragma unroll
    for (int t = 0; t < 4; t++) c[t] = make_float4(0.f, 0.f, 0.f, 0.f);

    for (int kh = 0; kh < 2; kh++) {
#pragma unroll
        for (int q = 0; q < 4; q++) {
            int idx = tid + q * 256;           // 0..1023
            int row = idx >> 4, k4 = idx & 15;
            float4 v = make_float4(0.f, 0.f, 0.f, 0.f);
            int grow = r0 + row;
            if (grow < n)
                v = *(const float4*)(x + (size_t)grow * IN_DIM + kh * 64 + k4 * 4);
            *(float4*)(xs + row * 68 + k4 * 4) =
                make_float4(f2tf(v.x), f2tf(v.y), f2tf(v.z), f2tf(v.w));
        }
#pragma unroll
        for (int q = 0; q < 4; q++) {
            int idx = tid + q * 256;
            int k = idx >> 4, c4 = idx & 15;
            float4 v = *(const float4*)(W + (size_t)(kh * 64 + k) * HC + c4 * 4);
            *(float4*)(ws + k * 72 + c4 * 4) =
                make_float4(f2tf(v.x), f2tf(v.y), f2tf(v.z), f2tf(v.w));
        }
        __syncthreads();
#pragma unroll
        for (int k8 = 0; k8 < 8; k8++) {
            int kb = k8 * 8;
            const float* xr = xs + (16 * wm + gid) * 68 + kb + tig;
            float a0 = xr[0];
            float a1 = xr[8 * 68];
            float a2 = xr[4];
            float a3 = xr[8 * 68 + 4];
            const float* wr = ws + (kb + tig) * 72 + 32 * wn + gid;
#pragma unroll
            for (int t = 0; t < 4; t++) {
                float b0 = wr[8 * t];
                float b1 = wr[4 * 72 + 8 * t];
                mma_tf32(c[t], a0, a1, a2, a3, b0, b1);
            }
        }
        __syncthreads();
    }

    // write C frags into xs [row][col 0..63]
    {
        int rlo = 16 * wm + gid;
        int cb  = 32 * wn + 2 * tig;
#pragma unroll
        for (int t = 0; t < 4; t++) {
            *(float2*)(xs + rlo * 68 + cb + 8 * t)       = make_float2(c[t].x, c[t].y);
            *(float2*)(xs + (rlo + 8) * 68 + cb + 8 * t) = make_float2(c[t].z, c[t].w);
        }
    }
    __syncthreads();

    // epilogue: thread = (row, quarter qd).
    //  - attention halves: quarter qd = head qd (cols 16qd..16qd+15)
    //  - xp2 store: pairs c in [8qd, 8qd+8): (xp[c], xp[c+32]) interleaved
    {
        int row = tid >> 2, qd = tid & 3;
        int grow = r0 + row;
        if (grow < n) {
            float4 v[4], s4[4], d4[4];
#pragma unroll
            for (int i = 0; i < 4; i++) {
                v[i]  = *(const float4*)(xs + row * 68 + qd * 16 + 4 * i);
                s4[i] = __ldg((const float4*)(att_src + qd * 16 + 4 * i));
                d4[i] = __ldg((const float4*)(att_dst + qd * 16 + 4 * i));
            }
            float as = 0.f, ad = 0.f;
#pragma unroll
            for (int i = 0; i < 4; i++) {
                as += v[i].x * s4[i].x + v[i].y * s4[i].y + v[i].z * s4[i].z + v[i].w * s4[i].w;
                ad += v[i].x * d4[i].x + v[i].y * d4[i].y + v[i].z * d4[i].z + v[i].w * d4[i].w;
            }
            ((float*)&g_as4[grow])[qd] = as;
            ((float*)&g_ad4[grow])[qd] = ad;
#pragma unroll
            for (int i = 0; i < 2; i++) {
                float4 A4 = *(const float4*)(xs + row * 68 + 8 * qd + 4 * i);
                float4 B4 = *(const float4*)(xs + row * 68 + 8 * qd + 32 + 4 * i);
                float* dst = g_xp + (size_t)grow * HC + 2 * (8 * qd + 4 * i);
                *(float4*)(dst)     = make_float4(A4.x, B4.x, A4.y, B4.y);
                *(float4*)(dst + 4) = make_float4(A4.z, B4.z, A4.w, B4.w);
            }
        }
    }
}

// ---------------- CSR histogram + fused edge_index float copy ----------------
__global__ void hist_kernel(const int* __restrict__ ei, int e, float* __restrict__ ei_out) {
    int t = blockIdx.x * blockDim.x + threadIdx.x;
    int base = t * 4;
    if (base + 3 < e) {
        int4 d4 = *(const int4*)(ei + e + base);
        atomicAdd(&g_cnt[d4.x], 1);
        atomicAdd(&g_cnt[d4.y], 1);
        atomicAdd(&g_cnt[d4.z], 1);
        atomicAdd(&g_cnt[d4.w], 1);
        if (ei_out) {
            int4 s4 = *(const int4*)(ei + base);
            *(float4*)(ei_out + base) =
                make_float4((float)s4.x, (float)s4.y, (float)s4.z, (float)s4.w);
            *(float4*)(ei_out + e + base) =
                make_float4((float)d4.x, (float)d4.y, (float)d4.z, (float)d4.w);
        }
    } else {
        for (int i = base; i < e; i++) {
            int s = ei[i], d = ei[e + i];
            atomicAdd(&g_cnt[d], 1);
            if (ei_out) { ei_out[i] = (float)s; ei_out[e + i] = (float)d; }
        }
    }
}

__global__ void scan1_kernel(int n) {
    __shared__ int sd[512];
    int t = threadIdx.x, i = blockIdx.x * 512 + t;
    int v = (i < n) ? g_cnt[i] : 0;
    sd[t] = v; __syncthreads();
    for (int off = 1; off < 512; off <<= 1) {
        int x = (t >= off) ? sd[t - off] : 0;
        __syncthreads();
        sd[t] += x;
        __syncthreads();
    }
    if (i < n) g_rowptr[i + 1] = sd[t];
    if (t == 511) g_bsum[blockIdx.x] = sd[511];
}

__global__ void scan2_kernel(int nb) {
    __shared__ int sd[512];
    int t = threadIdx.x;
    int v = (t < nb) ? g_bsum[t] : 0;
    sd[t] = v; __syncthreads();
    for (int off = 1; off < 512; off <<= 1) {
        int x = (t >= off) ? sd[t - off] : 0;
        __syncthreads();
        sd[t] += x;
        __syncthreads();
    }
    g_boff[t] = sd[t] - v;   // exclusive
}

// adds block offsets AND initializes fill cursors {start, 0}
__global__ void scan3_kernel(int n) {
    int t = threadIdx.x;
    int i = blockIdx.x * 512 + t;
    int inc = g_boff[blockIdx.x];
    int prev = 0;
    if (i < n && t > 0) prev = g_rowptr[i];     // scan1 value at i (pre-offset)
    __syncthreads();
    if (i < n) {
        g_rowptr[i + 1] += inc;
        g_fc[i] = make_int2(prev + inc, 0);
        if (i == 0) g_rowptr[0] = 0;
    }
}

__global__ void fill_kernel(const int* __restrict__ ei, int e) {
    int t = blockIdx.x * blockDim.x + threadIdx.x;
    if (t >= e) return;
    int s = ei[t], d = ei[e + t];
    int2* fc = &g_fc[d];
    int pos = atomicAdd(&fc->y, 1);
    g_csr_src[fc->x + pos] = s;
}

// ---------------- fused softmax + aggregation: one warp per dst node ----------------
// Interleaved xp2 layout: one LDG.64 per lane per edge (was 2x LDG.32).
__global__ __launch_bounds__(256) void aggregate_kernel(
    const float* __restrict__ bias, float* __restrict__ out, int n)
{
    __shared__ float sE[8][32][4];
    int w = (blockIdx.x * 256 + threadIdx.x) >> 5;
    int lane = threadIdx.x & 31, wl = threadIdx.x >> 5;
    if (w >= n) return;                 // uniform per warp

    int start = g_rowptr[w];
    int deg   = g_rowptr[w + 1] - start;
    float4 ad = g_ad4[w];

    float4 ds = make_float4(0.f, 0.f, 0.f, 0.f);
    float acc0 = 0.f, acc1 = 0.f;
    int h0 = lane >> 4;      // head of col=lane; col=lane+32 is head h0+2

    for (int base = 0; base < deg; base += 32) {
        int i = base + lane;
        int s = 0;
        float4 ev = make_float4(0.f, 0.f, 0.f, 0.f);
        if (i < deg) {
            s = g_csr_src[start + i];
            float4 a = g_as4[s];
            ev.x = __expf(lrelu(a.x + ad.x));
            ev.y = __expf(lrelu(a.y + ad.y));
            ev.z = __expf(lrelu(a.z + ad.z));
            ev.w = __expf(lrelu(a.w + ad.w));
            ds.x += ev.x; ds.y += ev.y; ds.z += ev.z; ds.w += ev.w;
        }
        sE[wl][lane][0] = ev.x; sE[wl][lane][1] = ev.y;
        sE[wl][lane][2] = ev.z; sE[wl][lane][3] = ev.w;
        __syncwarp();
        int cnt = min(32, deg - base);
        const float* sEj = &sE[wl][0][0];
#pragma unroll 8
        for (int j = 0; j < cnt; j++) {
            int sj = __shfl_sync(0xffffffffu, s, j);
            float e0 = sEj[j * 4 + h0];
            float e1 = sEj[j * 4 + 2 + h0];
            float2 f = __ldg((const float2*)(g_xp + (size_t)sj * HC + 2 * lane));
            acc0 = fmaf(f.x, e0, acc0);
            acc1 = fmaf(f.y, e1, acc1);
        }
        __syncwarp();
    }
#pragma unroll
    for (int o = 16; o >= 1; o >>= 1) {
        ds.x += __shfl_xor_sync(0xffffffffu, ds.x, o);
        ds.y += __shfl_xor_sync(0xffffffffu, ds.y, o);
        ds.z += __shfl_xor_sync(0xffffffffu, ds.z, o);
        ds.w += __shfl_xor_sync(0xffffffffu, ds.w, o);
    }
    float4 r;
    r.x = 1.f / (ds.x + 1e-16f); r.y = 1.f / (ds.y + 1e-16f);
    r.z = 1.f / (ds.z + 1e-16f); r.w = 1.f / (ds.w + 1e-16f);
    if (lane == 0) g_rcp4[w] = r;

    float r0 = h0 ? r.y : r.x;
    float r1 = h0 ? r.w : r.z;
    out[(size_t)w * HC + lane]      = acc0 * r0 + bias[lane];
    out[(size_t)w * HC + 32 + lane] = acc1 * r1 + bias[lane + 32];
}

// ---------------- alpha in edge order (coalesced) ----------------
__global__ __launch_bounds__(256) void alpha_kernel(
    const int* __restrict__ ei, int e, float* __restrict__ alpha_out)
{
    int t = blockIdx.x * blockDim.x + threadIdx.x;
    if (t >= e) return;
    int s = ei[t], d = ei[e + t];
    float4 a = g_as4[s];
    float4 b = g_ad4[d];
    float4 r = g_rcp4[d];
    float4 o;
    o.x = __expf(lrelu(a.x + b.x)) * r.x;
    o.y = __expf(lrelu(a.y + b.y)) * r.y;
    o.z = __expf(lrelu(a.z + b.z)) * r.z;
    o.w = __expf(lrelu(a.w + b.w)) * r.w;
    ((float4*)alpha_out)[t] = o;
}

extern "C" void kernel_launch(void* const* d_in, const int* in_sizes, int n_in,
                              void* d_out, int out_size) {
    const float* x       = (const float*)d_in[0];
    const float* W       = (const float*)d_in[1];
    const float* att_src = (const float*)d_in[2];
    const float* att_dst = (const float*)d_in[3];
    const float* bias    = (const float*)d_in[4];
    const int*   ei      = (const int*)d_in[5];
    float* out = (float*)d_out;

    int n = in_sizes[0] / IN_DIM;   // 100000
    int e = in_sizes[5] / 2;        // 1600000
    long nhc = (long)n * HC;
    int nb = (n + 511) / 512;

    float* ei_out = nullptr;
    float* alpha_out = nullptr;
    if ((long)out_size >= nhc + 2L * e)          ei_out    = out + nhc;
    if ((long)out_size >= nhc + 2L * e + 4L * e) alpha_out = out + nhc + 2L * e;

    // order chosen so the profiler's captured launch (index 3) is the GEMM
    init_kernel<<<(n + 511) / 512, 512>>>(n);
    hist_kernel<<<((e + 3) / 4 + 255) / 256, 256>>>(ei, e, ei_out);
    scan1_kernel<<<nb, 512>>>(n);
    gemm_kernel<<<(n + 63) / 64, 256>>>(x, W, att_src, att_dst, n);
    scan2_kernel<<<1, 512>>>(nb);
    scan3_kernel<<<nb, 512>>>(n);
    fill_kernel<<<(e + 255) / 256, 256>>>(ei, e);
    aggregate_kernel<<<(n * 32 + 255) / 256, 256>>>(bias, out, n);

    if (alpha_out)
        alpha_kernel<<<(e + 255) / 256, 256>>>(ei, e, alpha_out);
}